// round 2
// baseline (speedup 1.0000x reference)
#include <cuda_runtime.h>
#include <cuda_fp16.h>
#include <cstdint>

// Problem constants
#define OUT_F 4096
#define IN_F  4096
#define MROWS 8192
#define NPACK (OUT_F * IN_F / 2)

// GEMM tiling
#define MT 128
#define NT 128
#define KT 64                       // k-tile: 64 fp16 = 128B = one SW128 atom row
#define NKT (IN_F / KT)             // 64 k-tiles
#define STAGES 3
#define A_BYTES (MT * 128)          // 16384
#define B_BYTES (NT * 128)          // 16384
#define STAGE_BYTES (A_BYTES + B_BYTES)
#define SMEM_DYN (STAGES * STAGE_BYTES)   // 98304

// ---------------- scratch (static device globals) ----------------------------
__device__ __half g_w[(size_t)OUT_F * IN_F];   // 32 MB: int4 values as fp16 (no dequant)
__device__ __half g_x[(size_t)MROWS * IN_F];   // 64 MB: X in fp16
__device__ float  g_xsum[MROWS];               // fp32 row sums of X

// ---------------- helpers -----------------------------------------------------
__device__ __forceinline__ uint32_t s2u(const void* p) {
    uint32_t a;
    asm("{ .reg .u64 t; cvta.to.shared.u64 t, %1; cvt.u32.u64 %0, t; }" : "=r"(a) : "l"(p));
    return a;
}
__device__ __forceinline__ uint32_t swz(uint32_t off) { return off ^ ((off >> 3) & 0x70); }

__device__ __forceinline__ void cpa16(uint32_t dst, const void* src) {
    asm volatile("cp.async.cg.shared.global [%0], [%1], 16;" :: "r"(dst), "l"(src));
}
#define CP_COMMIT() asm volatile("cp.async.commit_group;" ::: "memory")
#define CP_WAIT2()  asm volatile("cp.async.wait_group 2;" ::: "memory")

__device__ __forceinline__ void ldm_x4(uint32_t* r, uint32_t addr) {
    asm volatile("ldmatrix.sync.aligned.m8n8.x4.shared.b16 {%0,%1,%2,%3}, [%4];"
                 : "=r"(r[0]), "=r"(r[1]), "=r"(r[2]), "=r"(r[3]) : "r"(addr));
}
__device__ __forceinline__ void mma16816(float* d, const uint32_t* a, const uint32_t* b) {
    asm volatile(
        "mma.sync.aligned.m16n8k16.row.col.f32.f16.f16.f32 "
        "{%0,%1,%2,%3}, {%4,%5,%6,%7}, {%8,%9}, {%0,%1,%2,%3};"
        : "+f"(d[0]), "+f"(d[1]), "+f"(d[2]), "+f"(d[3])
        : "r"(a[0]), "r"(a[1]), "r"(a[2]), "r"(a[3]), "r"(b[0]), "r"(b[1]));
}

// ------------------------- prep 1: unpack int4 -> fp16 ------------------------
__global__ void unpack_w(const int* __restrict__ packed) {
    int i = blockIdx.x * 256 + threadIdx.x;
    if (i < NPACK) {
        int b = packed[i];
        int lo = (b << 28) >> 28;
        int hi = (b << 24) >> 28;
        reinterpret_cast<__half2*>(g_w)[i] = __floats2half2_rn((float)lo, (float)hi);
    }
}

// ------------------- prep 2: X fp32 -> fp16 + row sums ------------------------
__global__ void conv_x(const float* __restrict__ x) {
    int row = blockIdx.x;
    const float* xr = x + (size_t)row * IN_F;
    __half* dr = g_x + (size_t)row * IN_F;
    float s = 0.f;
    for (int j = threadIdx.x; j < IN_F; j += 256) {
        float v = xr[j];
        dr[j] = __float2half_rn(v);
        s += v;
    }
    __shared__ float red[256];
    red[threadIdx.x] = s;
    __syncthreads();
    for (int o = 128; o > 0; o >>= 1) {
        if (threadIdx.x < o) red[threadIdx.x] += red[threadIdx.x + o];
        __syncthreads();
    }
    if (threadIdx.x == 0) g_xsum[row] = red[0];
}

// ------------------------------ main GEMM -------------------------------------
__global__ void __launch_bounds__(256, 2) gemm_q4(
    const float* __restrict__ scales, const float* __restrict__ zps,
    const float* __restrict__ bias, float* __restrict__ out)
{
    extern __shared__ char dyn_raw[];
    const uint32_t dynb = s2u(dyn_raw);

    const int tid = threadIdx.x;
    const int lane = tid & 31;
    const int wid = tid >> 5;
    const int warp_m = wid & 3;      // 4 warps along M -> 32 rows each
    const int warp_n = wid >> 2;     // 2 warps along N -> 64 cols each
    const int m_base = blockIdx.y * MT;
    const int n_base = blockIdx.x * NT;

    // producer: fill stage (kt % 3) with k-tile kt (8x 16B cp.async per thread)
    auto produce = [&](int kt) {
        uint32_t as = dynb + (kt % STAGES) * STAGE_BYTES;
        uint32_t bs = as + A_BYTES;
        int kc = kt * KT;
#pragma unroll
        for (int i = 0; i < 4; i++) {
            int lin = i * 256 + tid;
            int r = lin >> 3, c = lin & 7;
            cpa16(as + swz((uint32_t)(r * 128 + c * 16)),
                  g_x + ((size_t)(m_base + r) * IN_F + kc + c * 8));
        }
#pragma unroll
        for (int i = 0; i < 4; i++) {
            int lin = i * 256 + tid;
            int r = lin >> 3, c = lin & 7;
            cpa16(bs + swz((uint32_t)(r * 128 + c * 16)),
                  g_w + ((size_t)(n_base + r) * IN_F + kc + c * 8));
        }
    };

    // prologue: 3 stages in flight
    for (int kt = 0; kt < STAGES; kt++) { produce(kt); CP_COMMIT(); }

    float acc[2][8][4];
#pragma unroll
    for (int im = 0; im < 2; im++)
#pragma unroll
        for (int jn = 0; jn < 8; jn++)
#pragma unroll
            for (int r = 0; r < 4; r++) acc[im][jn][r] = 0.f;

    // lane-address components for ldmatrix
    const int a_lrow = lane & 15;           // A: lanes 0-15 chunk c0, 16-31 chunk c0+1
    const int a_lsel = lane >> 4;
    const int b_lrow = (lane & 7) + ((lane >> 4) << 3);  // B: 8-row groups
    const int b_lsel = (lane >> 3) & 1;

    for (int kt = 0; kt < NKT; kt++) {
        CP_WAIT2();
        __syncthreads();

        uint32_t as = dynb + (kt % STAGES) * STAGE_BYTES;
        uint32_t bs = as + A_BYTES;

#pragma unroll
        for (int ks = 0; ks < 4; ks++) {          // 4x k16 per k-tile
            uint32_t ra[2][4], rb[4][4];
#pragma unroll
            for (int im = 0; im < 2; im++) {
                int r0 = warp_m * 32 + im * 16;
                ldm_x4(ra[im], as + swz((uint32_t)((r0 + a_lrow) * 128 + (2 * ks + a_lsel) * 16)));
            }
#pragma unroll
            for (int jp = 0; jp < 4; jp++) {      // each x4 covers two n8 tiles
                int n0 = warp_n * 64 + jp * 16;
                ldm_x4(rb[jp], bs + swz((uint32_t)((n0 + b_lrow) * 128 + (2 * ks + b_lsel) * 16)));
            }
#pragma unroll
            for (int im = 0; im < 2; im++)
#pragma unroll
                for (int jn = 0; jn < 8; jn++)
                    mma16816(acc[im][jn], ra[im], &rb[jn >> 1][(jn & 1) * 2]);
        }

        __syncthreads();
        if (kt + STAGES < NKT) produce(kt + STAGES);
        CP_COMMIT();                               // empty group when past the end
    }

    // ---------------- epilogue: dequant + bias --------------------------------
    const int gid = lane >> 2;      // row within m16 tile
    const int tg  = lane & 3;       // col pair within n8 tile

#pragma unroll
    for (int im = 0; im < 2; im++) {
        int m0 = m_base + warp_m * 32 + im * 16 + gid;
        float xs0 = g_xsum[m0];
        float xs1 = g_xsum[m0 + 8];
#pragma unroll
        for (int jn = 0; jn < 8; jn++) {
            int n0 = n_base + warp_n * 64 + jn * 8 + tg * 2;
            int g = n0 >> 7;
            float sg = scales[g], zg = zps[g];
            float b0 = bias[n0], b1 = bias[n0 + 1];
            float sub0 = sg * zg * xs0, sub1 = sg * zg * xs1;

            float2 v0, v1;
            v0.x = sg * acc[im][jn][0] - sub0 + b0;
            v0.y = sg * acc[im][jn][1] - sub0 + b1;
            v1.x = sg * acc[im][jn][2] - sub1 + b0;
            v1.y = sg * acc[im][jn][3] - sub1 + b1;
            *reinterpret_cast<float2*>(out + (size_t)m0 * OUT_F + n0) = v0;
            *reinterpret_cast<float2*>(out + (size_t)(m0 + 8) * OUT_F + n0) = v1;
        }
    }
}

// ------------------------------- launch ---------------------------------------
extern "C" void kernel_launch(void* const* d_in, const int* in_sizes, int n_in,
                              void* d_out, int out_size) {
    const float* x      = (const float*)d_in[0];
    const int*   packed = (const int*)d_in[1];
    const float* scales = (const float*)d_in[2];
    const float* zps    = (const float*)d_in[3];
    const float* bias   = (const float*)d_in[4];
    float* out = (float*)d_out;

    unpack_w<<<NPACK / 256, 256>>>(packed);
    conv_x<<<MROWS, 256>>>(x);

    static int attr_set = 0;
    if (!attr_set) {
        cudaFuncSetAttribute(gemm_q4, cudaFuncAttributeMaxDynamicSharedMemorySize, SMEM_DYN);
        attr_set = 1;
    }
    dim3 grid(OUT_F / NT, MROWS / MT);   // (32, 64)
    gemm_q4<<<grid, 256, SMEM_DYN>>>(scales, zps, bias, out);
}

// round 3
// speedup vs baseline: 1.0059x; 1.0059x over previous
#include <cuda_runtime.h>
#include <cuda_fp16.h>
#include <cstdint>

// Problem constants
#define OUT_F 4096
#define IN_F  4096
#define MROWS 8192
#define NPACK (OUT_F * IN_F / 2)

// GEMM tiling: CTA 128x256, warp 64x64 (8 warps as 2x4)
#define MT 128
#define NT 256
#define KT 64                        // 64 fp16 = 128B = one SW128 atom row
#define NKT (IN_F / KT)              // 64 k-tiles
#define STAGES 4
#define A_BYTES (MT * 128)           // 16384
#define B_BYTES (NT * 128)           // 32768
#define STAGE_BYTES (A_BYTES + B_BYTES)      // 49152
#define SMEM_DYN (STAGES * STAGE_BYTES)      // 196608

// ---------------- scratch (static device globals) ----------------------------
__device__ __half g_w[(size_t)OUT_F * IN_F];   // 32 MB: int4 values as fp16
__device__ __half g_x[(size_t)MROWS * IN_F];   // 64 MB: X as fp16
__device__ float  g_xsum[MROWS];               // fp32 row sums of X

// ---------------- helpers -----------------------------------------------------
__device__ __forceinline__ uint32_t s2u(const void* p) {
    uint32_t a;
    asm("{ .reg .u64 t; cvta.to.shared.u64 t, %1; cvt.u32.u64 %0, t; }" : "=r"(a) : "l"(p));
    return a;
}
__device__ __forceinline__ uint32_t swz(uint32_t off) { return off ^ ((off >> 3) & 0x70); }

__device__ __forceinline__ void cpa16(uint32_t dst, const void* src) {
    asm volatile("cp.async.cg.shared.global [%0], [%1], 16;" :: "r"(dst), "l"(src));
}
#define CP_COMMIT() asm volatile("cp.async.commit_group;" ::: "memory")
#define CP_WAIT()   asm volatile("cp.async.wait_group %0;" :: "n"(STAGES - 1) : "memory")

__device__ __forceinline__ void ldm_x4(uint32_t* r, uint32_t addr) {
    asm volatile("ldmatrix.sync.aligned.m8n8.x4.shared.b16 {%0,%1,%2,%3}, [%4];"
                 : "=r"(r[0]), "=r"(r[1]), "=r"(r[2]), "=r"(r[3]) : "r"(addr));
}
__device__ __forceinline__ void mma16816(float* d, const uint32_t* a, const uint32_t* b) {
    asm volatile(
        "mma.sync.aligned.m16n8k16.row.col.f32.f16.f16.f32 "
        "{%0,%1,%2,%3}, {%4,%5,%6,%7}, {%8,%9}, {%0,%1,%2,%3};"
        : "+f"(d[0]), "+f"(d[1]), "+f"(d[2]), "+f"(d[3])
        : "r"(a[0]), "r"(a[1]), "r"(a[2]), "r"(a[3]), "r"(b[0]), "r"(b[1]));
}

// ------------------------- prep 1: unpack int4 -> fp16 ------------------------
__global__ void unpack_w(const int* __restrict__ packed) {
    int i = blockIdx.x * 256 + threadIdx.x;
    if (i < NPACK) {
        int b = packed[i];
        int lo = (b << 28) >> 28;
        int hi = (b << 24) >> 28;
        reinterpret_cast<__half2*>(g_w)[i] = __floats2half2_rn((float)lo, (float)hi);
    }
}

// ------------------- prep 2: X fp32 -> fp16 + row sums ------------------------
__global__ void conv_x(const float* __restrict__ x) {
    int row = blockIdx.x;
    const float* xr = x + (size_t)row * IN_F;
    __half* dr = g_x + (size_t)row * IN_F;
    float s = 0.f;
    for (int j = threadIdx.x; j < IN_F; j += 256) {
        float v = xr[j];
        dr[j] = __float2half_rn(v);
        s += v;
    }
    __shared__ float red[256];
    red[threadIdx.x] = s;
    __syncthreads();
    for (int o = 128; o > 0; o >>= 1) {
        if (threadIdx.x < o) red[threadIdx.x] += red[threadIdx.x + o];
        __syncthreads();
    }
    if (threadIdx.x == 0) g_xsum[row] = red[0];
}

// ------------------------------ main GEMM -------------------------------------
__global__ void __launch_bounds__(256, 1) gemm_q4(
    const float* __restrict__ scales, const float* __restrict__ zps,
    const float* __restrict__ bias, float* __restrict__ out)
{
    extern __shared__ char dyn_raw[];
    const uint32_t dynb = s2u(dyn_raw);

    const int tid = threadIdx.x;
    const int lane = tid & 31;
    const int wid = tid >> 5;
    const int warp_m = wid & 1;      // 2 warps along M -> 64 rows each
    const int warp_n = wid >> 1;     // 4 warps along N -> 64 cols each
    const int m_base = blockIdx.y * MT;
    const int n_base = blockIdx.x * NT;

    // producer: fill stage (kt % STAGES) with k-tile kt
    auto produce = [&](int kt) {
        uint32_t as = dynb + (kt % STAGES) * STAGE_BYTES;
        uint32_t bs = as + A_BYTES;
        int kc = kt * KT;
#pragma unroll
        for (int i = 0; i < 4; i++) {            // A: 128 rows x 128B
            int lin = i * 256 + tid;
            int r = lin >> 3, c = lin & 7;
            cpa16(as + swz((uint32_t)(r * 128 + c * 16)),
                  g_x + ((size_t)(m_base + r) * IN_F + kc + c * 8));
        }
#pragma unroll
        for (int i = 0; i < 8; i++) {            // B: 256 rows x 128B
            int lin = i * 256 + tid;
            int r = lin >> 3, c = lin & 7;
            cpa16(bs + swz((uint32_t)(r * 128 + c * 16)),
                  g_w + ((size_t)(n_base + r) * IN_F + kc + c * 8));
        }
    };

    // prologue
    for (int kt = 0; kt < STAGES; kt++) { produce(kt); CP_COMMIT(); }

    float acc[4][8][4];
#pragma unroll
    for (int im = 0; im < 4; im++)
#pragma unroll
        for (int jn = 0; jn < 8; jn++)
#pragma unroll
            for (int r = 0; r < 4; r++) acc[im][jn][r] = 0.f;

    const int a_lrow = lane & 15;
    const int a_lsel = lane >> 4;
    const int b_lrow = (lane & 7) + ((lane >> 4) << 3);
    const int b_lsel = (lane >> 3) & 1;

    for (int kt = 0; kt < NKT; kt++) {
        CP_WAIT();
        __syncthreads();

        uint32_t as = dynb + (kt % STAGES) * STAGE_BYTES;
        uint32_t bs = as + A_BYTES;

#pragma unroll
        for (int ks = 0; ks < 4; ks++) {         // 4x k16 per k-tile
            uint32_t ra[4][4], rb[4][4];
#pragma unroll
            for (int im = 0; im < 4; im++) {     // 64 rows = 4x m16
                int r0 = warp_m * 64 + im * 16;
                ldm_x4(ra[im], as + swz((uint32_t)((r0 + a_lrow) * 128 + (2 * ks + a_lsel) * 16)));
            }
#pragma unroll
            for (int jp = 0; jp < 4; jp++) {     // 64 cols = 4x n16
                int n0 = warp_n * 64 + jp * 16;
                ldm_x4(rb[jp], bs + swz((uint32_t)((n0 + b_lrow) * 128 + (2 * ks + b_lsel) * 16)));
            }
#pragma unroll
            for (int im = 0; im < 4; im++)
#pragma unroll
                for (int jn = 0; jn < 8; jn++)
                    mma16816(acc[im][jn], ra[im], &rb[jn >> 1][(jn & 1) * 2]);
        }

        __syncthreads();
        if (kt + STAGES < NKT) produce(kt + STAGES);
        CP_COMMIT();
    }

    // ---------------- epilogue: dequant + bias --------------------------------
    const int gid = lane >> 2;
    const int tg  = lane & 3;
    const int g0  = n_base >> 7;     // NT=256 spans groups g0 (cols 0-127), g0+1

#pragma unroll
    for (int im = 0; im < 4; im++) {
        int m0 = m_base + warp_m * 64 + im * 16 + gid;
        float xs0 = g_xsum[m0];
        float xs1 = g_xsum[m0 + 8];
#pragma unroll
        for (int jn = 0; jn < 8; jn++) {
            int ncol = warp_n * 64 + jn * 8 + tg * 2;
            int n0 = n_base + ncol;
            int g = g0 + (ncol >> 7);
            float sg = scales[g], zg = zps[g];
            float b0 = bias[n0], b1 = bias[n0 + 1];
            float sub0 = sg * zg * xs0, sub1 = sg * zg * xs1;

            float2 v0, v1;
            v0.x = sg * acc[im][jn][0] - sub0 + b0;
            v0.y = sg * acc[im][jn][1] - sub0 + b1;
            v1.x = sg * acc[im][jn][2] - sub1 + b0;
            v1.y = sg * acc[im][jn][3] - sub1 + b1;
            *reinterpret_cast<float2*>(out + (size_t)m0 * OUT_F + n0) = v0;
            *reinterpret_cast<float2*>(out + (size_t)(m0 + 8) * OUT_F + n0) = v1;
        }
    }
}

// ------------------------------- launch ---------------------------------------
extern "C" void kernel_launch(void* const* d_in, const int* in_sizes, int n_in,
                              void* d_out, int out_size) {
    const float* x      = (const float*)d_in[0];
    const int*   packed = (const int*)d_in[1];
    const float* scales = (const float*)d_in[2];
    const float* zps    = (const float*)d_in[3];
    const float* bias   = (const float*)d_in[4];
    float* out = (float*)d_out;

    unpack_w<<<NPACK / 256, 256>>>(packed);
    conv_x<<<MROWS, 256>>>(x);

    cudaFuncSetAttribute(gemm_q4, cudaFuncAttributeMaxDynamicSharedMemorySize, SMEM_DYN);
    dim3 grid(OUT_F / NT, MROWS / MT);   // (16, 64)
    gemm_q4<<<grid, 256, SMEM_DYN>>>(scales, zps, bias, out);
}

// round 5
// speedup vs baseline: 1.0384x; 1.0323x over previous
#include <cuda_runtime.h>
#include <cuda_fp16.h>
#include <cstdint>

// Problem constants
#define OUT_F 4096
#define IN_F  4096
#define MROWS 8192
#define NPACK (OUT_F * IN_F / 2)

// GEMM tiling: CTA 128x256, warp 64x64 (8 warps as 2x4)
#define MT 128
#define NT 256
#define KT 64                        // 64 fp16 = 128B = one SW128 atom row
#define NKT (IN_F / KT)              // 64 k-tiles
#define STAGES 4                     // 4 buffers, only 3 groups in flight
#define A_BYTES (MT * 128)
#define B_BYTES (NT * 128)
#define STAGE_BYTES (A_BYTES + B_BYTES)      // 49152
#define SMEM_DYN (STAGES * STAGE_BYTES)      // 196608

// ---------------- scratch (static device globals) ----------------------------
__device__ __half g_w[(size_t)OUT_F * IN_F];   // 32 MB: int4 values as fp16
__device__ __half g_x[(size_t)MROWS * IN_F];   // 64 MB: X as fp16
__device__ float  g_xsum[MROWS];               // fp32 row sums of X

// ---------------- helpers -----------------------------------------------------
__device__ __forceinline__ uint32_t h2u(__half2 h) {
    __half2_raw r = *reinterpret_cast<__half2_raw*>(&h);
    return (uint32_t)r.x | ((uint32_t)r.y << 16);
}
__device__ __forceinline__ uint32_t s2u(const void* p) {
    uint32_t a;
    asm("{ .reg .u64 t; cvta.to.shared.u64 t, %1; cvt.u32.u64 %0, t; }" : "=r"(a) : "l"(p));
    return a;
}
__device__ __forceinline__ uint32_t swz(uint32_t off) { return off ^ ((off >> 3) & 0x70); }

__device__ __forceinline__ void cpa16(uint32_t dst, const void* src) {
    asm volatile("cp.async.cg.shared.global [%0], [%1], 16;" :: "r"(dst), "l"(src));
}
#define CP_COMMIT() asm volatile("cp.async.commit_group;" ::: "memory")
#define CP_WAIT()   asm volatile("cp.async.wait_group 2;" ::: "memory")

__device__ __forceinline__ void ldm_x4(uint32_t* r, uint32_t addr) {
    asm volatile("ldmatrix.sync.aligned.m8n8.x4.shared.b16 {%0,%1,%2,%3}, [%4];"
                 : "=r"(r[0]), "=r"(r[1]), "=r"(r[2]), "=r"(r[3]) : "r"(addr));
}
__device__ __forceinline__ void mma16816(float* d, const uint32_t* a, const uint32_t* b) {
    asm volatile(
        "mma.sync.aligned.m16n8k16.row.col.f32.f16.f16.f32 "
        "{%0,%1,%2,%3}, {%4,%5,%6,%7}, {%8,%9}, {%0,%1,%2,%3};"
        : "+f"(d[0]), "+f"(d[1]), "+f"(d[2]), "+f"(d[3])
        : "r"(a[0]), "r"(a[1]), "r"(a[2]), "r"(a[3]), "r"(b[0]), "r"(b[1]));
}

// ------------------------- prep 1: unpack int4 -> fp16 ------------------------
// 4 packed int32 (each holding one signed byte = 2 nibbles) per thread, uint4 I/O.
__global__ void unpack_w(const int* __restrict__ packed) {
    int i = blockIdx.x * 256 + threadIdx.x;     // i indexes groups of 4 ints
    const int4 v = reinterpret_cast<const int4*>(packed)[i];
    uint32_t o[4];
    {
        int b = v.x;
        o[0] = h2u(__floats2half2_rn((float)((b << 28) >> 28), (float)((b << 24) >> 28)));
        b = v.y;
        o[1] = h2u(__floats2half2_rn((float)((b << 28) >> 28), (float)((b << 24) >> 28)));
        b = v.z;
        o[2] = h2u(__floats2half2_rn((float)((b << 28) >> 28), (float)((b << 24) >> 28)));
        b = v.w;
        o[3] = h2u(__floats2half2_rn((float)((b << 28) >> 28), (float)((b << 24) >> 28)));
    }
    reinterpret_cast<uint4*>(g_w)[i] = make_uint4(o[0], o[1], o[2], o[3]);
}

// ------------------- prep 2: X fp32 -> fp16 + row sums ------------------------
__global__ void conv_x(const float* __restrict__ x) {
    const int row = blockIdx.x;
    const int tid = threadIdx.x;
    const float4* xr = reinterpret_cast<const float4*>(x + (size_t)row * IN_F);
    uint2* dr = reinterpret_cast<uint2*>(g_x + (size_t)row * IN_F);
    float s = 0.f;
#pragma unroll
    for (int i = 0; i < 4; i++) {                 // 4 float4 = 16 floats/thread
        int j = i * 256 + tid;
        float4 v = xr[j];
        s += v.x + v.y + v.z + v.w;
        uint2 h;
        h.x = h2u(__floats2half2_rn(v.x, v.y));
        h.y = h2u(__floats2half2_rn(v.z, v.w));
        dr[j] = h;
    }
    // warp reduce then smem reduce (8 warps)
#pragma unroll
    for (int o = 16; o > 0; o >>= 1) s += __shfl_xor_sync(0xffffffffu, s, o);
    __shared__ float red[8];
    if ((tid & 31) == 0) red[tid >> 5] = s;
    __syncthreads();
    if (tid == 0) {
        float t = 0.f;
#pragma unroll
        for (int w = 0; w < 8; w++) t += red[w];
        g_xsum[row] = t;
    }
}

// ------------------------------ main GEMM -------------------------------------
__global__ void __launch_bounds__(256, 1) gemm_q4(
    const float* __restrict__ scales, const float* __restrict__ zps,
    const float* __restrict__ bias, float* __restrict__ out)
{
    extern __shared__ char dyn_raw[];
    const uint32_t dynb = s2u(dyn_raw);

    const int tid = threadIdx.x;
    const int lane = tid & 31;
    const int wid = tid >> 5;
    const int warp_m = wid & 1;      // 2 warps along M -> 64 rows each
    const int warp_n = wid >> 1;     // 4 warps along N -> 64 cols each
    const int m_base = blockIdx.y * MT;
    const int n_base = blockIdx.x * NT;

    auto produce = [&](int kt) {
        uint32_t as = dynb + (kt & (STAGES - 1)) * STAGE_BYTES;
        uint32_t bs = as + A_BYTES;
        int kc = kt * KT;
#pragma unroll
        for (int i = 0; i < 4; i++) {            // A: 128 rows x 128B
            int lin = i * 256 + tid;
            int r = lin >> 3, c = lin & 7;
            cpa16(as + swz((uint32_t)(r * 128 + c * 16)),
                  g_x + ((size_t)(m_base + r) * IN_F + kc + c * 8));
        }
#pragma unroll
        for (int i = 0; i < 8; i++) {            // B: 256 rows x 128B
            int lin = i * 256 + tid;
            int r = lin >> 3, c = lin & 7;
            cpa16(bs + swz((uint32_t)(r * 128 + c * 16)),
                  g_w + ((size_t)(n_base + r) * IN_F + kc + c * 8));
        }
    };

    // prologue: 3 groups in flight (4th buffer is the write-ahead slot)
    for (int kt = 0; kt < 3; kt++) { produce(kt); CP_COMMIT(); }

    float acc[4][8][4];
#pragma unroll
    for (int im = 0; im < 4; im++)
#pragma unroll
        for (int jn = 0; jn < 8; jn++)
#pragma unroll
            for (int r = 0; r < 4; r++) acc[im][jn][r] = 0.f;

    const int a_lrow = lane & 15;
    const int a_lsel = lane >> 4;
    const int b_lrow = (lane & 7) + ((lane >> 4) << 3);
    const int b_lsel = (lane >> 3) & 1;

    for (int kt = 0; kt < NKT; kt++) {
        CP_WAIT();
        __syncthreads();
        // write-ahead into slot (kt-1)&3: all readers passed the barrier above
        if (kt + 3 < NKT) produce(kt + 3);
        CP_COMMIT();

        uint32_t as = dynb + (kt & (STAGES - 1)) * STAGE_BYTES;
        uint32_t bs = as + A_BYTES;

        // register double-buffered fragments across the 4 k16 steps
        uint32_t ra[2][4][4], rb[2][4][4];
#pragma unroll
        for (int im = 0; im < 4; im++) {
            int r0 = warp_m * 64 + im * 16;
            ldm_x4(ra[0][im], as + swz((uint32_t)((r0 + a_lrow) * 128 + a_lsel * 16)));
        }
#pragma unroll
        for (int jp = 0; jp < 4; jp++) {
            int n0 = warp_n * 64 + jp * 16;
            ldm_x4(rb[0][jp], bs + swz((uint32_t)((n0 + b_lrow) * 128 + b_lsel * 16)));
        }

#pragma unroll
        for (int ks = 0; ks < 4; ks++) {
            const int cur = ks & 1, nxt = cur ^ 1;
            if (ks < 3) {
#pragma unroll
                for (int im = 0; im < 4; im++) {
                    int r0 = warp_m * 64 + im * 16;
                    ldm_x4(ra[nxt][im],
                           as + swz((uint32_t)((r0 + a_lrow) * 128 + (2 * (ks + 1) + a_lsel) * 16)));
                }
#pragma unroll
                for (int jp = 0; jp < 4; jp++) {
                    int n0 = warp_n * 64 + jp * 16;
                    ldm_x4(rb[nxt][jp],
                           bs + swz((uint32_t)((n0 + b_lrow) * 128 + (2 * (ks + 1) + b_lsel) * 16)));
                }
            }
#pragma unroll
            for (int im = 0; im < 4; im++)
#pragma unroll
                for (int jn = 0; jn < 8; jn++)
                    mma16816(acc[im][jn], ra[cur][im], &rb[cur][jn >> 1][(jn & 1) * 2]);
        }
        // NOTE: no second __syncthreads — next iteration's barrier protects reuse
    }

    // ---------------- epilogue: dequant + bias --------------------------------
    const int gid = lane >> 2;
    const int tg  = lane & 3;
    const int g0  = n_base >> 7;

#pragma unroll
    for (int im = 0; im < 4; im++) {
        int m0 = m_base + warp_m * 64 + im * 16 + gid;
        float xs0 = g_xsum[m0];
        float xs1 = g_xsum[m0 + 8];
#pragma unroll
        for (int jn = 0; jn < 8; jn++) {
            int ncol = warp_n * 64 + jn * 8 + tg * 2;
            int n0 = n_base + ncol;
            int g = g0 + (ncol >> 7);
            float sg = scales[g], zg = zps[g];
            float b0 = bias[n0], b1 = bias[n0 + 1];
            float sub0 = sg * zg * xs0, sub1 = sg * zg * xs1;

            float2 v0, v1;
            v0.x = sg * acc[im][jn][0] - sub0 + b0;
            v0.y = sg * acc[im][jn][1] - sub0 + b1;
            v1.x = sg * acc[im][jn][2] - sub1 + b0;
            v1.y = sg * acc[im][jn][3] - sub1 + b1;
            *reinterpret_cast<float2*>(out + (size_t)m0 * OUT_F + n0) = v0;
            *reinterpret_cast<float2*>(out + (size_t)(m0 + 8) * OUT_F + n0) = v1;
        }
    }
}

// ------------------------------- launch ---------------------------------------
extern "C" void kernel_launch(void* const* d_in, const int* in_sizes, int n_in,
                              void* d_out, int out_size) {
    const float* x      = (const float*)d_in[0];
    const int*   packed = (const int*)d_in[1];
    const float* scales = (const float*)d_in[2];
    const float* zps    = (const float*)d_in[3];
    const float* bias   = (const float*)d_in[4];
    float* out = (float*)d_out;

    unpack_w<<<NPACK / 4 / 256, 256>>>(packed);
    conv_x<<<MROWS, 256>>>(x);

    cudaFuncSetAttribute(gemm_q4, cudaFuncAttributeMaxDynamicSharedMemorySize, SMEM_DYN);
    dim3 grid(OUT_F / NT, MROWS / MT);   // (16, 64)
    gemm_q4<<<grid, 256, SMEM_DYN>>>(scales, zps, bias, out);
}

// round 6
// speedup vs baseline: 1.1341x; 1.0922x over previous
#include <cuda_runtime.h>
#include <cuda_fp16.h>
#include <cstdint>

// Problem constants
#define OUT_F 4096
#define IN_F  4096
#define MROWS 8192
#define NPACK (OUT_F * IN_F / 2)

// GEMM tiling: CTA 128x256, warp 64x64 (8 warps as 2x4)
#define MT 128
#define NT 256
#define KT 64
#define NKT (IN_F / KT)              // 64 k-tiles
#define STAGES 4                     // 4 buffers, 3 groups in flight
#define A_BYTES (MT * 128)
#define B_BYTES (NT * 128)
#define STAGE_BYTES (A_BYTES + B_BYTES)      // 49152
#define SMEM_DYN (STAGES * STAGE_BYTES)      // 196608

// ---------------- scratch ------------------------------------------------------
__device__ __half g_w[(size_t)OUT_F * IN_F];
__device__ __half g_x[(size_t)MROWS * IN_F];
__device__ float  g_xsum[MROWS];

// ---------------- helpers ------------------------------------------------------
__device__ __forceinline__ uint32_t h2u(__half2 h) {
    __half2_raw r = *reinterpret_cast<__half2_raw*>(&h);
    return (uint32_t)r.x | ((uint32_t)r.y << 16);
}
__device__ __forceinline__ uint32_t s2u(const void* p) {
    uint32_t a;
    asm("{ .reg .u64 t; cvta.to.shared.u64 t, %1; cvt.u32.u64 %0, t; }" : "=r"(a) : "l"(p));
    return a;
}
__device__ __forceinline__ uint32_t swz(uint32_t off) { return off ^ ((off >> 3) & 0x70); }

__device__ __forceinline__ void cpa16(uint32_t dst, const void* src) {
    asm volatile("cp.async.cg.shared.global [%0], [%1], 16;" :: "r"(dst), "l"(src));
}
#define CP_COMMIT() asm volatile("cp.async.commit_group;" ::: "memory")
#define CP_WAIT2()  asm volatile("cp.async.wait_group 2;" ::: "memory")

__device__ __forceinline__ void ldm_x4(uint32_t* r, uint32_t addr) {
    asm volatile("ldmatrix.sync.aligned.m8n8.x4.shared.b16 {%0,%1,%2,%3}, [%4];"
                 : "=r"(r[0]), "=r"(r[1]), "=r"(r[2]), "=r"(r[3]) : "r"(addr));
}
__device__ __forceinline__ void mma16816(float* d, const uint32_t* a, const uint32_t* b) {
    asm volatile(
        "mma.sync.aligned.m16n8k16.row.col.f32.f16.f16.f32 "
        "{%0,%1,%2,%3}, {%4,%5,%6,%7}, {%8,%9}, {%0,%1,%2,%3};"
        : "+f"(d[0]), "+f"(d[1]), "+f"(d[2]), "+f"(d[3])
        : "r"(a[0]), "r"(a[1]), "r"(a[2]), "r"(a[3]), "r"(b[0]), "r"(b[1]));
}

// ---------------- merged prep: unpack W + convert X + row sums ------------------
// blocks [0, MROWS): conv_x for row = blockIdx.x
// blocks [MROWS, MROWS+8192): unpack chunk
#define PREP_UNPACK_BLOCKS (NPACK / 4 / 256)   // 8192
__global__ void prep(const float* __restrict__ x, const int* __restrict__ packed) {
    const int tid = threadIdx.x;
    if (blockIdx.x < MROWS) {
        const int row = blockIdx.x;
        const float4* xr = reinterpret_cast<const float4*>(x + (size_t)row * IN_F);
        uint2* dr = reinterpret_cast<uint2*>(g_x + (size_t)row * IN_F);
        float s = 0.f;
#pragma unroll
        for (int i = 0; i < 4; i++) {
            int j = i * 256 + tid;
            float4 v = xr[j];
            s += v.x + v.y + v.z + v.w;
            uint2 h;
            h.x = h2u(__floats2half2_rn(v.x, v.y));
            h.y = h2u(__floats2half2_rn(v.z, v.w));
            dr[j] = h;
        }
#pragma unroll
        for (int o = 16; o > 0; o >>= 1) s += __shfl_xor_sync(0xffffffffu, s, o);
        __shared__ float red[8];
        if ((tid & 31) == 0) red[tid >> 5] = s;
        __syncthreads();
        if (tid == 0) {
            float t = 0.f;
#pragma unroll
            for (int w = 0; w < 8; w++) t += red[w];
            g_xsum[row] = t;
        }
    } else {
        int i = (blockIdx.x - MROWS) * 256 + tid;
        const int4 v = reinterpret_cast<const int4*>(packed)[i];
        uint32_t o[4];
        int b = v.x;
        o[0] = h2u(__floats2half2_rn((float)((b << 28) >> 28), (float)((b << 24) >> 28)));
        b = v.y;
        o[1] = h2u(__floats2half2_rn((float)((b << 28) >> 28), (float)((b << 24) >> 28)));
        b = v.z;
        o[2] = h2u(__floats2half2_rn((float)((b << 28) >> 28), (float)((b << 24) >> 28)));
        b = v.w;
        o[3] = h2u(__floats2half2_rn((float)((b << 28) >> 28), (float)((b << 24) >> 28)));
        reinterpret_cast<uint4*>(g_w)[i] = make_uint4(o[0], o[1], o[2], o[3]);
    }
}

// ------------------------------ main GEMM ---------------------------------------
__global__ void __launch_bounds__(256, 1) gemm_q4(
    const float* __restrict__ scales, const float* __restrict__ zps,
    const float* __restrict__ bias, float* __restrict__ out)
{
    extern __shared__ char dyn_raw[];
    const uint32_t dynb = s2u(dyn_raw);

    const int tid = threadIdx.x;
    const int lane = tid & 31;
    const int wid = tid >> 5;
    const int warp_m = wid & 1;
    const int warp_n = wid >> 1;
    const int m_base = blockIdx.y * MT;
    const int n_base = blockIdx.x * NT;

    // producer pointers held in registers, bumped by 128B per k-tile
    const int ar = (tid >> 3) * 4;              // covers 4 rows per i-iter via +32 rows
    const int ac = tid & 7;
    const char* a_src = reinterpret_cast<const char*>(
        g_x + ((size_t)(m_base + (tid >> 3)) * IN_F + ac * 8));
    const char* b_src = reinterpret_cast<const char*>(
        g_w + ((size_t)(n_base + (tid >> 3)) * IN_F + ac * 8));
    const uint32_t a_dst0 = swz((uint32_t)((tid >> 3) * 128 + ac * 16));

    auto produce = [&](int kt) {
        uint32_t as = dynb + (kt & (STAGES - 1)) * STAGE_BYTES;
        uint32_t bs = as + A_BYTES;
        size_t koff = (size_t)kt * (KT * 2);    // byte offset along K
#pragma unroll
        for (int i = 0; i < 4; i++) {           // A: rows tid>>3 + 32*i
            cpa16(as + a_dst0 + i * 32 * 128,
                  a_src + koff + (size_t)i * 32 * IN_F * 2);
        }
#pragma unroll
        for (int i = 0; i < 8; i++) {           // B: rows tid>>3 + 32*i
            cpa16(bs + a_dst0 + i * 32 * 128,
                  b_src + koff + (size_t)i * 32 * IN_F * 2);
        }
    };

    for (int kt = 0; kt < 3; kt++) { produce(kt); CP_COMMIT(); }

    float acc[4][8][4];
#pragma unroll
    for (int im = 0; im < 4; im++)
#pragma unroll
        for (int jn = 0; jn < 8; jn++)
#pragma unroll
            for (int r = 0; r < 4; r++) acc[im][jn][r] = 0.f;

    const int a_lrow = lane & 15;
    const int a_lsel = lane >> 4;
    const int b_lrow = (lane & 7) + ((lane >> 4) << 3);
    const int b_lsel = (lane >> 3) & 1;

    // fragment buffers, software-pipelined across k-tiles
    uint32_t ra[2][4][4], rb[2][4][4];

    auto ldA = [&](uint32_t* dst, uint32_t as, int ks) {
#pragma unroll
        for (int im = 0; im < 4; im++) {
            int r0 = warp_m * 64 + im * 16;
            ldm_x4(dst + im * 4, as + swz((uint32_t)((r0 + a_lrow) * 128 + (2 * ks + a_lsel) * 16)));
        }
    };
    auto ldB = [&](uint32_t* dst, uint32_t bs, int ks) {
#pragma unroll
        for (int jp = 0; jp < 4; jp++) {
            int n0 = warp_n * 64 + jp * 16;
            ldm_x4(dst + jp * 4, bs + swz((uint32_t)((n0 + b_lrow) * 128 + (2 * ks + b_lsel) * 16)));
        }
    };

    // first k-tile: wait, sync, prime fragments
    CP_WAIT2();
    __syncthreads();
    {
        uint32_t as = dynb, bs = dynb + A_BYTES;
        ldA(&ra[0][0][0], as, 0);
        ldB(&rb[0][0][0], bs, 0);
    }

    for (int kt = 0; kt < NKT; kt++) {
        // write-ahead into slot (kt-1)&3
        if (kt + 3 < NKT) produce(kt + 3);
        CP_COMMIT();

        uint32_t as = dynb + (kt & (STAGES - 1)) * STAGE_BYTES;
        uint32_t bs = as + A_BYTES;

#pragma unroll
        for (int ks = 0; ks < 4; ks++) {
            const int cur = ks & 1, nxt = cur ^ 1;
            if (ks < 3) {
                ldA(&ra[nxt][0][0], as, ks + 1);
                ldB(&rb[nxt][0][0], bs, ks + 1);
            }
#pragma unroll
            for (int im = 0; im < 4; im++)
#pragma unroll
                for (int jn = 0; jn < 8; jn++)
                    mma16816(acc[im][jn], ra[cur][im], &rb[cur][jn >> 1][(jn & 1) * 2]);

            // at the last ks, prefetch next k-tile's first fragments
            if (ks == 3 && kt + 1 < NKT) {
                CP_WAIT2();                 // groups through kt+1 complete
                __syncthreads();            // all warps done reading slot (kt+1-? ) / protect producer
                uint32_t as2 = dynb + ((kt + 1) & (STAGES - 1)) * STAGE_BYTES;
                uint32_t bs2 = as2 + A_BYTES;
                ldA(&ra[0][0][0], as2, 0);
                ldB(&rb[0][0][0], bs2, 0);
            }
        }
    }

    // ---------------- epilogue: dequant + bias ------------------------------------
    const int gid = lane >> 2;
    const int tg  = lane & 3;
    const int g0  = n_base >> 7;

#pragma unroll
    for (int im = 0; im < 4; im++) {
        int m0 = m_base + warp_m * 64 + im * 16 + gid;
        float xs0 = g_xsum[m0];
        float xs1 = g_xsum[m0 + 8];
#pragma unroll
        for (int jn = 0; jn < 8; jn++) {
            int ncol = warp_n * 64 + jn * 8 + tg * 2;
            int n0 = n_base + ncol;
            int g = g0 + (ncol >> 7);
            float sg = scales[g], zg = zps[g];
            float b0 = bias[n0], b1 = bias[n0 + 1];
            float sub0 = sg * zg * xs0, sub1 = sg * zg * xs1;

            float2 v0, v1;
            v0.x = sg * acc[im][jn][0] - sub0 + b0;
            v0.y = sg * acc[im][jn][1] - sub0 + b1;
            v1.x = sg * acc[im][jn][2] - sub1 + b0;
            v1.y = sg * acc[im][jn][3] - sub1 + b1;
            *reinterpret_cast<float2*>(out + (size_t)m0 * OUT_F + n0) = v0;
            *reinterpret_cast<float2*>(out + (size_t)(m0 + 8) * OUT_F + n0) = v1;
        }
    }
}

// ------------------------------- launch -------------------------------------------
extern "C" void kernel_launch(void* const* d_in, const int* in_sizes, int n_in,
                              void* d_out, int out_size) {
    const float* x      = (const float*)d_in[0];
    const int*   packed = (const int*)d_in[1];
    const float* scales = (const float*)d_in[2];
    const float* zps    = (const float*)d_in[3];
    const float* bias   = (const float*)d_in[4];
    float* out = (float*)d_out;

    prep<<<MROWS + PREP_UNPACK_BLOCKS, 256>>>(x, packed);

    cudaFuncSetAttribute(gemm_q4, cudaFuncAttributeMaxDynamicSharedMemorySize, SMEM_DYN);
    dim3 grid(OUT_F / NT, MROWS / MT);   // (16, 64)
    gemm_q4<<<grid, 256, SMEM_DYN>>>(scales, zps, bias, out);
}

// round 7
// speedup vs baseline: 1.1566x; 1.0198x over previous
#include <cuda_runtime.h>
#include <cuda_fp16.h>
#include <cstdint>

// Problem constants
#define OUT_F 4096
#define IN_F  4096
#define MROWS 8192
#define NPACK (OUT_F * IN_F / 2)

// GEMM tiling: CTA 128x128, warp 64x32 (8 warps as 2x4), 2 CTAs/SM
#define MT 128
#define NT 128
#define KT 64
#define NKT (IN_F / KT)              // 64 k-tiles
#define STAGES 3                     // 3 buffers, 2 groups in flight
#define A_BYTES (MT * 128)           // 16384
#define B_BYTES (NT * 128)           // 16384
#define STAGE_BYTES (A_BYTES + B_BYTES)      // 32768
#define SMEM_DYN (STAGES * STAGE_BYTES)      // 98304 per CTA -> 2 CTAs/SM

// ---------------- scratch ------------------------------------------------------
__device__ __half g_w[(size_t)OUT_F * IN_F];
__device__ __half g_x[(size_t)MROWS * IN_F];
__device__ float  g_xsum[MROWS];

// ---------------- helpers ------------------------------------------------------
__device__ __forceinline__ uint32_t h2u(__half2 h) {
    __half2_raw r = *reinterpret_cast<__half2_raw*>(&h);
    return (uint32_t)r.x | ((uint32_t)r.y << 16);
}
__device__ __forceinline__ uint32_t s2u(const void* p) {
    uint32_t a;
    asm("{ .reg .u64 t; cvta.to.shared.u64 t, %1; cvt.u32.u64 %0, t; }" : "=r"(a) : "l"(p));
    return a;
}
__device__ __forceinline__ uint32_t swz(uint32_t off) { return off ^ ((off >> 3) & 0x70); }

__device__ __forceinline__ void cpa16(uint32_t dst, const void* src) {
    asm volatile("cp.async.cg.shared.global [%0], [%1], 16;" :: "r"(dst), "l"(src));
}
#define CP_COMMIT() asm volatile("cp.async.commit_group;" ::: "memory")
#define CP_WAIT1()  asm volatile("cp.async.wait_group 1;" ::: "memory")

__device__ __forceinline__ void ldm_x4(uint32_t* r, uint32_t addr) {
    asm volatile("ldmatrix.sync.aligned.m8n8.x4.shared.b16 {%0,%1,%2,%3}, [%4];"
                 : "=r"(r[0]), "=r"(r[1]), "=r"(r[2]), "=r"(r[3]) : "r"(addr));
}
__device__ __forceinline__ void mma16816(float* d, const uint32_t* a, const uint32_t* b) {
    asm volatile(
        "mma.sync.aligned.m16n8k16.row.col.f32.f16.f16.f32 "
        "{%0,%1,%2,%3}, {%4,%5,%6,%7}, {%8,%9}, {%0,%1,%2,%3};"
        : "+f"(d[0]), "+f"(d[1]), "+f"(d[2]), "+f"(d[3])
        : "r"(a[0]), "r"(a[1]), "r"(a[2]), "r"(a[3]), "r"(b[0]), "r"(b[1]));
}

// ---------------- merged prep: unpack W + convert X + row sums ------------------
#define PREP_UNPACK_BLOCKS (NPACK / 4 / 256)   // 8192
__global__ void prep(const float* __restrict__ x, const int* __restrict__ packed) {
    const int tid = threadIdx.x;
    if (blockIdx.x < MROWS) {
        const int row = blockIdx.x;
        const float4* xr = reinterpret_cast<const float4*>(x + (size_t)row * IN_F);
        uint2* dr = reinterpret_cast<uint2*>(g_x + (size_t)row * IN_F);
        float s = 0.f;
#pragma unroll
        for (int i = 0; i < 4; i++) {
            int j = i * 256 + tid;
            float4 v = xr[j];
            s += v.x + v.y + v.z + v.w;
            uint2 h;
            h.x = h2u(__floats2half2_rn(v.x, v.y));
            h.y = h2u(__floats2half2_rn(v.z, v.w));
            dr[j] = h;
        }
#pragma unroll
        for (int o = 16; o > 0; o >>= 1) s += __shfl_xor_sync(0xffffffffu, s, o);
        __shared__ float red[8];
        if ((tid & 31) == 0) red[tid >> 5] = s;
        __syncthreads();
        if (tid == 0) {
            float t = 0.f;
#pragma unroll
            for (int w = 0; w < 8; w++) t += red[w];
            g_xsum[row] = t;
        }
    } else {
        int i = (blockIdx.x - MROWS) * 256 + tid;
        const int4 v = reinterpret_cast<const int4*>(packed)[i];
        uint32_t o[4];
        int b = v.x;
        o[0] = h2u(__floats2half2_rn((float)((b << 28) >> 28), (float)((b << 24) >> 28)));
        b = v.y;
        o[1] = h2u(__floats2half2_rn((float)((b << 28) >> 28), (float)((b << 24) >> 28)));
        b = v.z;
        o[2] = h2u(__floats2half2_rn((float)((b << 28) >> 28), (float)((b << 24) >> 28)));
        b = v.w;
        o[3] = h2u(__floats2half2_rn((float)((b << 28) >> 28), (float)((b << 24) >> 28)));
        reinterpret_cast<uint4*>(g_w)[i] = make_uint4(o[0], o[1], o[2], o[3]);
    }
}

// ------------------------------ main GEMM ---------------------------------------
__global__ void __launch_bounds__(256, 2) gemm_q4(
    const float* __restrict__ scales, const float* __restrict__ zps,
    const float* __restrict__ bias, float* __restrict__ out)
{
    extern __shared__ char dyn_raw[];
    const uint32_t dynb = s2u(dyn_raw);

    const int tid = threadIdx.x;
    const int lane = tid & 31;
    const int wid = tid >> 5;
    const int warp_m = wid & 1;      // 2 warps along M -> 64 rows each
    const int warp_n = wid >> 1;     // 4 warps along N -> 32 cols each
    const int m_base = blockIdx.y * MT;
    const int n_base = blockIdx.x * NT;

    // producer source pointers in registers
    const int prow = tid >> 3;                  // 0..31
    const int pcol = tid & 7;
    const char* a_src = reinterpret_cast<const char*>(
        g_x + ((size_t)(m_base + prow) * IN_F + pcol * 8));
    const char* b_src = reinterpret_cast<const char*>(
        g_w + ((size_t)(n_base + prow) * IN_F + pcol * 8));
    const uint32_t p_dst0 = swz((uint32_t)(prow * 128 + pcol * 16));

    auto produce = [&](int kt) {
        uint32_t as = dynb + (kt % STAGES) * STAGE_BYTES;
        uint32_t bs = as + A_BYTES;
        size_t koff = (size_t)kt * (KT * 2);
#pragma unroll
        for (int i = 0; i < 4; i++)
            cpa16(as + p_dst0 + i * 32 * 128, a_src + koff + (size_t)i * 32 * IN_F * 2);
#pragma unroll
        for (int i = 0; i < 4; i++)
            cpa16(bs + p_dst0 + i * 32 * 128, b_src + koff + (size_t)i * 32 * IN_F * 2);
    };

    produce(0); CP_COMMIT();
    produce(1); CP_COMMIT();

    float acc[4][4][4];
#pragma unroll
    for (int im = 0; im < 4; im++)
#pragma unroll
        for (int jn = 0; jn < 4; jn++)
#pragma unroll
            for (int r = 0; r < 4; r++) acc[im][jn][r] = 0.f;

    const int a_lrow = lane & 15;
    const int a_lsel = lane >> 4;
    const int b_lrow = (lane & 7) + ((lane >> 4) << 3);
    const int b_lsel = (lane >> 3) & 1;

    for (int kt = 0; kt < NKT; kt++) {
        CP_WAIT1();
        __syncthreads();
        // write-ahead into slot (kt+2)%3 == (kt-1)%3: readers passed the barrier
        if (kt + 2 < NKT) produce(kt + 2);
        CP_COMMIT();

        uint32_t as = dynb + (kt % STAGES) * STAGE_BYTES;
        uint32_t bs = as + A_BYTES;

#pragma unroll
        for (int ks = 0; ks < 4; ks++) {
            uint32_t ra[4][4], rb[2][4];
#pragma unroll
            for (int im = 0; im < 4; im++) {
                int r0 = warp_m * 64 + im * 16;
                ldm_x4(ra[im], as + swz((uint32_t)((r0 + a_lrow) * 128 + (2 * ks + a_lsel) * 16)));
            }
#pragma unroll
            for (int jp = 0; jp < 2; jp++) {
                int n0 = warp_n * 32 + jp * 16;
                ldm_x4(rb[jp], bs + swz((uint32_t)((n0 + b_lrow) * 128 + (2 * ks + b_lsel) * 16)));
            }
#pragma unroll
            for (int im = 0; im < 4; im++)
#pragma unroll
                for (int jn = 0; jn < 4; jn++)
                    mma16816(acc[im][jn], ra[im], &rb[jn >> 1][(jn & 1) * 2]);
        }
    }

    // ---------------- epilogue: dequant + bias ------------------------------------
    const int gid = lane >> 2;
    const int tg  = lane & 3;
    const int g   = n_base >> 7;     // NT=128 -> exactly one quant group per CTA
    const float sg = scales[g], zg = zps[g];
    const float szg = sg * zg;

#pragma unroll
    for (int im = 0; im < 4; im++) {
        int m0 = m_base + warp_m * 64 + im * 16 + gid;
        float xs0 = g_xsum[m0];
        float xs1 = g_xsum[m0 + 8];
        float sub0 = szg * xs0, sub1 = szg * xs1;
#pragma unroll
        for (int jn = 0; jn < 4; jn++) {
            int n0 = n_base + warp_n * 32 + jn * 8 + tg * 2;
            float b0 = bias[n0], b1 = bias[n0 + 1];

            float2 v0, v1;
            v0.x = sg * acc[im][jn][0] - sub0 + b0;
            v0.y = sg * acc[im][jn][1] - sub0 + b1;
            v1.x = sg * acc[im][jn][2] - sub1 + b0;
            v1.y = sg * acc[im][jn][3] - sub1 + b1;
            *reinterpret_cast<float2*>(out + (size_t)m0 * OUT_F + n0) = v0;
            *reinterpret_cast<float2*>(out + (size_t)(m0 + 8) * OUT_F + n0) = v1;
        }
    }
}

// ------------------------------- launch -------------------------------------------
extern "C" void kernel_launch(void* const* d_in, const int* in_sizes, int n_in,
                              void* d_out, int out_size) {
    const float* x      = (const float*)d_in[0];
    const int*   packed = (const int*)d_in[1];
    const float* scales = (const float*)d_in[2];
    const float* zps    = (const float*)d_in[3];
    const float* bias   = (const float*)d_in[4];
    float* out = (float*)d_out;

    prep<<<MROWS + PREP_UNPACK_BLOCKS, 256>>>(x, packed);

    cudaFuncSetAttribute(gemm_q4, cudaFuncAttributeMaxDynamicSharedMemorySize, SMEM_DYN);
    dim3 grid(OUT_F / NT, MROWS / MT);   // (32, 64)
    gemm_q4<<<grid, 256, SMEM_DYN>>>(scales, zps, bias, out);
}